// round 3
// baseline (speedup 1.0000x reference)
#include <cuda_runtime.h>
#include <cuda_bf16.h>
#include <cstdint>

// ---------------------------------------------------------------------------
// YOLOv3 post-process: decode + top-k + class-shifted greedy NMS
// B=32 images, C=255 channels, G=64 grid, 3 anchors, 80 classes
// ---------------------------------------------------------------------------

#define BATCH 32
#define GRID 64
#define GG   4096          // 64*64
#define NBOX 12288         // GG*3
#define NCLS 80
#define TOPK 1024
#define TIECAP 2048
#define MONO_NEGINF 0x007FFFFFu   // mono encoding of -inf float

// -------------------- device scratch (no allocations allowed) --------------
// g_det rows stored at STORAGE index m = a*GG + s (coalesced writes).
__device__ float              g_det[(size_t)BATCH * NBOX * 8];     // x1,y1,x2,y2,conf,maxval,clsidx,pad
__device__ unsigned long long g_key[(size_t)BATCH * NBOX];         // mono<<32 | ~n (logical n)
__device__ unsigned           g_mono[(size_t)BATCH * NBOX];        // mono only (for histogram sweep)
__device__ float              g_cand[(size_t)BATCH * TOPK * 8];    // sx1,sy1,sx2,sy2,area,cls,valid,pad
__device__ int                g_topidx[BATCH * TOPK];              // storage index m of ranked box
__device__ unsigned           g_validbits[BATCH * 32];             // conf>0.5 bit per rank
__device__ unsigned           g_mask[(size_t)BATCH * TOPK * 32];   // suppression bitmask rows
__device__ unsigned           g_rownz[BATCH * 32];                 // per-image "row has nonzero mask" bits

// -------------------- K1: decode -------------------------------------------
__global__ void k_decode(const float* __restrict__ in)
{
    int b = blockIdx.y;
    int s = blockIdx.x * blockDim.x + threadIdx.x;   // 0..4095
    const float* base = in + (size_t)b * 255 * GG + s;

    int p = ((s & 63) << 6) | (s >> 6);              // logical grid index (g2<<6)|g1

    #pragma unroll
    for (int a = 0; a < 3; a++) {
        const float* cb = base + (size_t)a * 85 * GG;
        float t0 = cb[0 * GG];
        float t1 = cb[1 * GG];
        float t2 = cb[2 * GG];
        float t3 = cb[3 * GG];
        float t4 = cb[4 * GG];

        // argmax over 80 class scores, first-max wins (matches jnp.argmax)
        float best = cb[5 * GG];
        int   bi   = 0;
        #pragma unroll 8
        for (int d = 1; d < NCLS; d++) {
            float v = cb[(5 + d) * GG];
            if (v > best) { best = v; bi = d; }
        }

        int n = 3 * p + a;                           // logical row index
        float xo = (float)((n >> 6) & 63);
        float yo = (float)(n & 63);

        float cx = __fadd_rn(t0, xo);
        float cy = __fadd_rn(t1, yo);
        float hw = __fmul_rn(t2, 0.5f);
        float hh = __fmul_rn(t3, 0.5f);

        float conf = 1.0f / (1.0f + expf(-t4));

        int m = a * GG + s;                          // storage index (coalesced)
        float4* dr = reinterpret_cast<float4*>(&g_det[(((size_t)b * NBOX) + m) * 8]);
        dr[0] = make_float4(__fsub_rn(cx, hw), __fsub_rn(cy, hh),
                            __fadd_rn(cx, hw), __fadd_rn(cy, hh));
        dr[1] = make_float4(conf, best, (float)bi, 0.0f);

        // ranking key: monotone-encoded logit (exact order == conf order),
        // logit<=0 -> shared -inf bucket (stable by index, like jax top_k).
        unsigned mono;
        if (t4 > 0.0f) mono = __float_as_uint(t4) ^ 0x80000000u;
        else           mono = MONO_NEGINF;
        g_mono[(size_t)b * NBOX + m] = mono;
        g_key[(size_t)b * NBOX + m] =
            ((unsigned long long)mono << 32) | (unsigned)(~(unsigned)n);
    }
}

// -------------------- K2: exact top-1024 select + sort ----------------------
// One block per image. One 12-bit histogram over mono finds the pivot bin;
// keys above the bin compact directly, the (small) pivot-bin tie set is sorted
// exactly by full 64-bit key and topped up. Then a 1024-wide bitonic sort.
__global__ void k_select()
{
    int b    = blockIdx.x;
    int tid  = threadIdx.x;   // 1024 threads
    int lane = tid & 31;
    int warp = tid >> 5;

    __shared__ unsigned            hist[4096];
    __shared__ unsigned long long  s_sel[TOPK];
    __shared__ unsigned long long  s_tie[TIECAP];
    __shared__ unsigned            s_T1, s_need, s_cnt_hi, s_cnt_tie;

    const unsigned* monos = g_mono + (size_t)b * NBOX;
    const unsigned long long* keys = g_key + (size_t)b * NBOX;

    for (int q = tid; q < 4096; q += 1024) hist[q] = 0;
    if (tid == 0) { s_cnt_hi = 0; s_cnt_tie = 0; }
    __syncthreads();

    // histogram over top-12 bits of mono; negatives (all -> bin of MONO_NEGINF)
    // are warp-aggregated to avoid the single-bin atomic storm.
    const uint4* m4 = reinterpret_cast<const uint4*>(monos);
    #pragma unroll
    for (int it = 0; it < 3; it++) {
        uint4 v = m4[tid + it * 1024];
        unsigned vals[4] = {v.x, v.y, v.z, v.w};
        #pragma unroll
        for (int q = 0; q < 4; q++) {
            unsigned m = vals[q];
            bool pos = m >= 0x80000000u;
            unsigned nb = __ballot_sync(0xffffffffu, !pos);
            if (pos) atomicAdd(&hist[m >> 20], 1u);
            if (lane == 0 && nb) atomicAdd(&hist[MONO_NEGINF >> 20], __popc(nb));
        }
    }
    __syncthreads();

    // warp 0: descending threshold search (lane owns 128 consecutive-desc bins)
    if (warp == 0) {
        int basebin = 4095 - 128 * lane;
        unsigned tot = 0;
        for (int q = 0; q < 128; q++) tot += hist[basebin - q];
        unsigned inc = tot;
        #pragma unroll
        for (int off = 1; off < 32; off <<= 1) {
            unsigned vv = __shfl_up_sync(0xffffffffu, inc, off);
            if (lane >= off) inc += vv;
        }
        unsigned excl = inc - tot;
        if (excl < TOPK && TOPK <= inc) {
            unsigned run = excl; int T = basebin;
            for (int q = 0; q < 128; q++) {
                unsigned h = hist[basebin - q];
                if (run + h >= TOPK) { T = basebin - q; break; }
                run += h;
            }
            s_T1 = (unsigned)T;
            s_need = TOPK - run;     // to take from the pivot bin
        }
    }
    __syncthreads();
    unsigned T1 = s_T1, need = s_need;

    // compact: above-bin keys straight in; pivot-bin keys to tie buffer
    for (int e = tid; e < NBOX; e += 1024) {
        unsigned long long k = keys[e];
        unsigned m12 = (unsigned)(k >> 52);
        if (m12 > T1) {
            unsigned pos = atomicAdd(&s_cnt_hi, 1u);
            s_sel[pos] = k;                       // pos < 1024 by construction
        } else if (m12 == T1) {
            unsigned pos = atomicAdd(&s_cnt_tie, 1u);
            if (pos < TIECAP) s_tie[pos] = k;
        }
    }
    __syncthreads();
    unsigned cnt_hi = s_cnt_hi;                   // == TOPK - need
    unsigned tcnt = s_cnt_tie < TIECAP ? s_cnt_tie : TIECAP;

    // adaptive bitonic (descending) of the tie buffer
    unsigned Tpad = 2;
    while (Tpad < tcnt) Tpad <<= 1;
    for (unsigned t = tid; t < Tpad; t += 1024)
        if (t >= tcnt) s_tie[t] = 0ull;
    __syncthreads();
    for (unsigned kk = 2; kk <= Tpad; kk <<= 1) {
        for (unsigned j = kk >> 1; j > 0; j >>= 1) {
            for (unsigned i = tid; i < Tpad; i += 1024) {
                unsigned ixj = i ^ j;
                if (ixj > i) {
                    unsigned long long va = s_tie[i];
                    unsigned long long vb = s_tie[ixj];
                    if (((i & kk) == 0) ? (va < vb) : (va > vb)) {
                        s_tie[i] = vb; s_tie[ixj] = va;
                    }
                }
            }
            __syncthreads();
        }
    }
    for (unsigned t = tid; t < need; t += 1024)
        s_sel[cnt_hi + t] = s_tie[t];
    __syncthreads();

    // full bitonic sort descending (1024 elements, 1024 threads)
    for (unsigned k = 2; k <= TOPK; k <<= 1) {
        for (unsigned j = k >> 1; j > 0; j >>= 1) {
            unsigned i = tid;
            unsigned ixj = i ^ j;
            if (ixj > i) {
                unsigned long long va = s_sel[i];
                unsigned long long vb = s_sel[ixj];
                if (((i & k) == 0) ? (va < vb) : (va > vb)) {
                    s_sel[i] = vb; s_sel[ixj] = va;
                }
            }
            __syncthreads();
        }
    }

    // emit candidate row at rank=tid
    unsigned long long kk = s_sel[tid];
    unsigned n    = ~(unsigned)kk;            // logical box index
    unsigned mono = (unsigned)(kk >> 32);
    bool valid = mono > 0x80000000u;          // conf > 0.5  <=>  logit > 0

    // logical n -> storage m
    int a  = (int)(n % 3u);
    int p  = (int)(n / 3u);
    int sI = ((p & 63) << 6) | (p >> 6);
    int m  = a * GG + sI;

    const float4* dr = reinterpret_cast<const float4*>(&g_det[((size_t)b * NBOX + m) * 8]);
    float4 d0 = dr[0], d1 = dr[1];
    float cls = d1.z;
    float off = __fmul_rn(cls, 10000.0f);
    float sx1 = __fadd_rn(d0.x, off);
    float sy1 = __fadd_rn(d0.y, off);
    float sx2 = __fadd_rn(d0.z, off);
    float sy2 = __fadd_rn(d0.w, off);
    float area = __fmul_rn(__fsub_rn(sx2, sx1), __fsub_rn(sy2, sy1));

    float4* cr = reinterpret_cast<float4*>(&g_cand[((size_t)b * TOPK + tid) * 8]);
    cr[0] = make_float4(sx1, sy1, sx2, sy2);
    cr[1] = make_float4(area, cls, valid ? 1.0f : 0.0f, 0.0f);
    g_topidx[b * TOPK + tid] = m;

    unsigned vb2 = __ballot_sync(0xffffffffu, valid);
    if (lane == 0) g_validbits[b * 32 + warp] = vb2;
}

// -------------------- K3: pairwise suppression bitmask ----------------------
// grid (32 row-tiles, 32 images), 1024 threads = 32 warps.
// Warp r handles row i = rt*32+r; lane owns column j = w*32+lane each step:
// consecutive-j shared loads (conflict-free) + __ballot_sync builds the word.
__global__ void k_mask()
{
    int rt  = blockIdx.x;
    int b   = blockIdx.y;
    int tid = threadIdx.x;
    int warp = tid >> 5;
    int lane = tid & 31;

    __shared__ float sx1[TOPK], sy1[TOPK], sx2[TOPK], sy2[TOPK], sar[TOPK], scl[TOPK];
    __shared__ unsigned s_any[32];

    for (int e = tid; e < TOPK; e += 1024) {
        const float4* cr = reinterpret_cast<const float4*>(&g_cand[((size_t)b * TOPK + e) * 8]);
        float4 c0 = cr[0], c1 = cr[1];
        sx1[e] = c0.x; sy1[e] = c0.y; sx2[e] = c0.z;
        sy2[e] = c0.w; sar[e] = c1.x; scl[e] = c1.y;
    }
    __syncthreads();

    int i = rt * 32 + warp;
    float ax1 = sx1[i], ay1 = sy1[i], ax2 = sx2[i], ay2 = sy2[i];
    float aa = sar[i], ac = scl[i];

    unsigned myword = 0;
    #pragma unroll 4
    for (int w = 0; w < 32; w++) {
        int j = (w << 5) + lane;
        bool sup = false;
        if (j > i && scl[j] == ac) {   // class offset 10000 => cross-class IoU can never pass
            float lx = fmaxf(ax1, sx1[j]);
            float ly = fmaxf(ay1, sy1[j]);
            float rx = fminf(ax2, sx2[j]);
            float ry = fminf(ay2, sy2[j]);
            float ww = fmaxf(__fsub_rn(rx, lx), 0.0f);
            float hh = fmaxf(__fsub_rn(ry, ly), 0.0f);
            float inter = __fmul_rn(ww, hh);
            float denom = __fadd_rn(__fsub_rn(__fadd_rn(aa, sar[j]), inter), 1e-9f);
            float iou   = __fdiv_rn(inter, denom);
            sup = iou > 0.4f;
        }
        unsigned word = __ballot_sync(0xffffffffu, sup);
        if (w == lane) myword = word;
    }
    g_mask[(((size_t)b * TOPK) + i) * 32 + lane] = myword;

    unsigned nzb = __ballot_sync(0xffffffffu, myword != 0u);
    if (lane == 0) s_any[warp] = nzb;
    __syncthreads();
    if (warp == 0) {
        unsigned bits = __ballot_sync(0xffffffffu, s_any[lane] != 0u);
        if (lane == 0) g_rownz[b * 32 + rt] = bits;
    }
}

// -------------------- K4: resolve + emit (fused, 1 block/image) -------------
// mask[i] only sets bits j>i, so only rows with nonzero mask rows can change
// state. Preload those rows' masks to smem in parallel, resolve with 1 warp
// entirely from registers/LDS, then all 1024 threads emit.
__global__ void k_final(float* __restrict__ out, int out_size)
{
    int b   = blockIdx.x;
    int tid = threadIdx.x;   // 1024 threads

    __shared__ unsigned       s_rem[32];
    __shared__ unsigned short s_rows[TOPK];
    __shared__ int            s_R;
    __shared__ unsigned       s_masks[256][32];

    // ordered list of nonzero-mask rows (warp 0)
    if (tid < 32) {
        unsigned nz = g_rownz[b * 32 + tid];
        int cnt = __popc(nz);
        int inc = cnt;
        #pragma unroll
        for (int off = 1; off < 32; off <<= 1) {
            int v = __shfl_up_sync(0xffffffffu, inc, off);
            if (tid >= off) inc += v;
        }
        int o = inc - cnt;
        unsigned t = nz;
        while (t) { int r = __ffs(t) - 1; t &= t - 1; s_rows[o++] = (unsigned short)(tid * 32 + r); }
        if (tid == 31) s_R = inc;
    }
    __syncthreads();
    int R  = s_R;
    int RL = R < 256 ? R : 256;

    // parallel preload of the (few) needed mask rows
    for (int t = tid; t < RL * 32; t += 1024)
        s_masks[t >> 5][t & 31] = g_mask[((size_t)b * TOPK + s_rows[t >> 5]) * 32 + (t & 31)];
    __syncthreads();

    // serial resolve (1 warp, register-resident state)
    if (tid < 32) {
        int lane = tid;
        unsigned rem = 0;
        unsigned validw = g_validbits[b * 32 + lane];
        for (int k2 = 0; k2 < R; k2++) {
            int i = s_rows[k2];
            unsigned w  = __shfl_sync(0xffffffffu, rem,    i >> 5);
            unsigned vw = __shfl_sync(0xffffffffu, validw, i >> 5);
            bool act = !((w >> (i & 31)) & 1u) && ((vw >> (i & 31)) & 1u);
            if (act)
                rem |= (k2 < 256) ? s_masks[k2][lane]
                                  : g_mask[((size_t)b * TOPK + i) * 32 + lane];
        }
        s_rem[lane] = rem;
    }
    __syncthreads();

    // emit
    int j = tid;
    bool keep = ((g_validbits[b * 32 + (j >> 5)] >> (j & 31)) & 1u)
             && !((s_rem[j >> 5] >> (j & 31)) & 1u);

    int m = g_topidx[b * TOPK + j];
    const float4* dr = reinterpret_cast<const float4*>(&g_det[((size_t)b * NBOX + m) * 8]);
    float4 d0 = dr[0], d1 = dr[1];
    float o7[7] = {d0.x, d0.y, d0.z, d0.w, d1.x, d1.y, d1.z};

    size_t basep = ((size_t)b * TOPK + j) * 7;
    #pragma unroll
    for (int k = 0; k < 7; k++)
        out[basep + k] = keep ? __fmul_rn(8.0f, o7[k]) : 0.0f;

    if (out_size >= BATCH * TOPK * 7 + BATCH * TOPK)
        out[(size_t)BATCH * TOPK * 7 + (size_t)b * TOPK + j] = keep ? 1.0f : 0.0f;
}

// -------------------- launch -----------------------------------------------
extern "C" void kernel_launch(void* const* d_in, const int* in_sizes, int n_in,
                              void* d_out, int out_size)
{
    const float* in = (const float*)d_in[0];
    float* out = (float*)d_out;

    k_decode<<<dim3(16, BATCH), 256>>>(in);
    k_select<<<BATCH, 1024>>>();
    k_mask<<<dim3(32, BATCH), 1024>>>();
    k_final<<<BATCH, 1024>>>(out, out_size);
}

// round 4
// speedup vs baseline: 1.0080x; 1.0080x over previous
#include <cuda_runtime.h>
#include <cuda_bf16.h>
#include <cstdint>

// ---------------------------------------------------------------------------
// YOLOv3 post-process: decode + top-k + class-shifted greedy NMS
// B=32 images, C=255 channels, G=64 grid, 3 anchors, 80 classes
// ---------------------------------------------------------------------------

#define BATCH 32
#define GRID 64
#define GG   4096          // 64*64
#define GG4  1024          // GG/4
#define NBOX 12288         // GG*3
#define NCLS 80
#define TOPK 1024
#define TIECAP 2048
#define MONO_NEGINF 0x007FFFFFu   // mono encoding of -inf float

// -------------------- device scratch (no allocations allowed) --------------
// g_det rows stored at STORAGE index m = a*GG + s (coalesced writes).
__device__ float              g_det[(size_t)BATCH * NBOX * 8];     // x1,y1,x2,y2,conf,maxval,clsidx,pad
__device__ unsigned long long g_key[(size_t)BATCH * NBOX];         // mono<<32 | ~n (logical n)
__device__ unsigned           g_mono[(size_t)BATCH * NBOX];        // mono only (for histogram sweep)
__device__ float              g_cand[(size_t)BATCH * TOPK * 8];    // sx1,sy1,sx2,sy2,area,cls,valid,pad
__device__ int                g_topidx[BATCH * TOPK];              // storage index m of ranked box
__device__ unsigned           g_validbits[BATCH * 32];             // conf>0.5 bit per rank
__device__ unsigned           g_mask[(size_t)BATCH * TOPK * 32];   // suppression bitmask rows
__device__ unsigned           g_rownz[BATCH * 32];                 // per-image "row has nonzero mask" bits

// -------------------- K1: decode (vectorized, one anchor per block) --------
// grid (8, 3, 32), 128 threads. Thread handles 4 consecutive s via float4:
// 4 independent argmax chains, 4x fewer LDG, 16B loads, contiguous stores.
__global__ void k_decode(const float* __restrict__ in)
{
    int a  = blockIdx.y;                 // anchor
    int b  = blockIdx.z;                 // image
    int s4 = blockIdx.x * blockDim.x + threadIdx.x;   // 0..1023

    const float4* cb = reinterpret_cast<const float4*>(
        in + ((size_t)b * 255 + (size_t)a * 85) * GG) + s4;

    float4 t0 = cb[0 * GG4];
    float4 t1 = cb[1 * GG4];
    float4 t2 = cb[2 * GG4];
    float4 t3 = cb[3 * GG4];
    float4 t4 = cb[4 * GG4];

    // argmax over 80 class scores, 4 independent chains (first-max wins)
    float4 best = cb[5 * GG4];
    int bix = 0, biy = 0, biz = 0, biw = 0;
    #pragma unroll 4
    for (int d = 1; d < NCLS; d++) {
        float4 v = cb[(5 + d) * GG4];
        if (v.x > best.x) { best.x = v.x; bix = d; }
        if (v.y > best.y) { best.y = v.y; biy = d; }
        if (v.z > best.z) { best.z = v.z; biz = d; }
        if (v.w > best.w) { best.w = v.w; biw = d; }
    }

    float t0a[4] = {t0.x, t0.y, t0.z, t0.w};
    float t1a[4] = {t1.x, t1.y, t1.z, t1.w};
    float t2a[4] = {t2.x, t2.y, t2.z, t2.w};
    float t3a[4] = {t3.x, t3.y, t3.z, t3.w};
    float t4a[4] = {t4.x, t4.y, t4.z, t4.w};
    float bsta[4] = {best.x, best.y, best.z, best.w};
    int   bia[4]  = {bix, biy, biz, biw};

    int s0 = s4 * 4;
    int m0 = a * GG + s0;                // storage base (contiguous for e=0..3)
    float4* dr = reinterpret_cast<float4*>(&g_det[(((size_t)b * NBOX) + m0) * 8]);
    unsigned long long* kp = &g_key[(size_t)b * NBOX + m0];
    unsigned*           mp = &g_mono[(size_t)b * NBOX + m0];

    #pragma unroll
    for (int e = 0; e < 4; e++) {
        int s = s0 + e;
        int p = ((s & 63) << 6) | (s >> 6);          // logical grid index
        int n = 3 * p + a;                           // logical row index
        float xo = (float)((n >> 6) & 63);
        float yo = (float)(n & 63);

        float cx = __fadd_rn(t0a[e], xo);
        float cy = __fadd_rn(t1a[e], yo);
        float hw = __fmul_rn(t2a[e], 0.5f);
        float hh = __fmul_rn(t3a[e], 0.5f);
        float lg = t4a[e];
        float conf = 1.0f / (1.0f + expf(-lg));

        dr[2 * e + 0] = make_float4(__fsub_rn(cx, hw), __fsub_rn(cy, hh),
                                    __fadd_rn(cx, hw), __fadd_rn(cy, hh));
        dr[2 * e + 1] = make_float4(conf, bsta[e], (float)bia[e], 0.0f);

        unsigned mono;
        if (lg > 0.0f) mono = __float_as_uint(lg) ^ 0x80000000u;
        else           mono = MONO_NEGINF;
        mp[e] = mono;
        kp[e] = ((unsigned long long)mono << 32) | (unsigned)(~(unsigned)n);
    }
}

// -------------------- K2: exact top-1024 select + sort ----------------------
// One block per image. One 12-bit histogram over mono finds the pivot bin;
// keys above the bin compact directly, the (small) pivot-bin tie set is sorted
// exactly by full 64-bit key and topped up. Then a 1024-wide bitonic sort.
__global__ void k_select()
{
    int b    = blockIdx.x;
    int tid  = threadIdx.x;   // 1024 threads
    int lane = tid & 31;
    int warp = tid >> 5;

    __shared__ unsigned            hist[4096];
    __shared__ unsigned long long  s_sel[TOPK];
    __shared__ unsigned long long  s_tie[TIECAP];
    __shared__ unsigned            s_T1, s_need, s_cnt_hi, s_cnt_tie;

    const unsigned* monos = g_mono + (size_t)b * NBOX;
    const unsigned long long* keys = g_key + (size_t)b * NBOX;

    for (int q = tid; q < 4096; q += 1024) hist[q] = 0;
    if (tid == 0) { s_cnt_hi = 0; s_cnt_tie = 0; }
    __syncthreads();

    // histogram over top-12 bits of mono; negatives (all -> bin of MONO_NEGINF)
    // are warp-aggregated to avoid the single-bin atomic storm.
    const uint4* m4 = reinterpret_cast<const uint4*>(monos);
    #pragma unroll
    for (int it = 0; it < 3; it++) {
        uint4 v = m4[tid + it * 1024];
        unsigned vals[4] = {v.x, v.y, v.z, v.w};
        #pragma unroll
        for (int q = 0; q < 4; q++) {
            unsigned m = vals[q];
            bool pos = m >= 0x80000000u;
            unsigned nb = __ballot_sync(0xffffffffu, !pos);
            if (pos) atomicAdd(&hist[m >> 20], 1u);
            if (lane == 0 && nb) atomicAdd(&hist[MONO_NEGINF >> 20], __popc(nb));
        }
    }
    __syncthreads();

    // warp 0: descending threshold search (lane owns 128 consecutive-desc bins)
    if (warp == 0) {
        int basebin = 4095 - 128 * lane;
        unsigned tot = 0;
        for (int q = 0; q < 128; q++) tot += hist[basebin - q];
        unsigned inc = tot;
        #pragma unroll
        for (int off = 1; off < 32; off <<= 1) {
            unsigned vv = __shfl_up_sync(0xffffffffu, inc, off);
            if (lane >= off) inc += vv;
        }
        unsigned excl = inc - tot;
        if (excl < TOPK && TOPK <= inc) {
            unsigned run = excl; int T = basebin;
            for (int q = 0; q < 128; q++) {
                unsigned h = hist[basebin - q];
                if (run + h >= TOPK) { T = basebin - q; break; }
                run += h;
            }
            s_T1 = (unsigned)T;
            s_need = TOPK - run;     // to take from the pivot bin
        }
    }
    __syncthreads();
    unsigned T1 = s_T1, need = s_need;

    // compact: above-bin keys straight in; pivot-bin keys to tie buffer
    for (int e = tid; e < NBOX; e += 1024) {
        unsigned long long k = keys[e];
        unsigned m12 = (unsigned)(k >> 52);
        if (m12 > T1) {
            unsigned pos = atomicAdd(&s_cnt_hi, 1u);
            s_sel[pos] = k;                       // pos < 1024 by construction
        } else if (m12 == T1) {
            unsigned pos = atomicAdd(&s_cnt_tie, 1u);
            if (pos < TIECAP) s_tie[pos] = k;
        }
    }
    __syncthreads();
    unsigned cnt_hi = s_cnt_hi;                   // == TOPK - need
    unsigned tcnt = s_cnt_tie < TIECAP ? s_cnt_tie : TIECAP;

    // adaptive bitonic (descending) of the tie buffer
    unsigned Tpad = 2;
    while (Tpad < tcnt) Tpad <<= 1;
    for (unsigned t = tid; t < Tpad; t += 1024)
        if (t >= tcnt) s_tie[t] = 0ull;
    __syncthreads();
    for (unsigned kk = 2; kk <= Tpad; kk <<= 1) {
        for (unsigned j = kk >> 1; j > 0; j >>= 1) {
            for (unsigned i = tid; i < Tpad; i += 1024) {
                unsigned ixj = i ^ j;
                if (ixj > i) {
                    unsigned long long va = s_tie[i];
                    unsigned long long vb = s_tie[ixj];
                    if (((i & kk) == 0) ? (va < vb) : (va > vb)) {
                        s_tie[i] = vb; s_tie[ixj] = va;
                    }
                }
            }
            __syncthreads();
        }
    }
    for (unsigned t = tid; t < need; t += 1024)
        s_sel[cnt_hi + t] = s_tie[t];
    __syncthreads();

    // full bitonic sort descending (1024 elements, 1024 threads)
    for (unsigned k = 2; k <= TOPK; k <<= 1) {
        for (unsigned j = k >> 1; j > 0; j >>= 1) {
            unsigned i = tid;
            unsigned ixj = i ^ j;
            if (ixj > i) {
                unsigned long long va = s_sel[i];
                unsigned long long vb = s_sel[ixj];
                if (((i & k) == 0) ? (va < vb) : (va > vb)) {
                    s_sel[i] = vb; s_sel[ixj] = va;
                }
            }
            __syncthreads();
        }
    }

    // emit candidate row at rank=tid
    unsigned long long kk = s_sel[tid];
    unsigned n    = ~(unsigned)kk;            // logical box index
    unsigned mono = (unsigned)(kk >> 32);
    bool valid = mono > 0x80000000u;          // conf > 0.5  <=>  logit > 0

    // logical n -> storage m
    int a  = (int)(n % 3u);
    int p  = (int)(n / 3u);
    int sI = ((p & 63) << 6) | (p >> 6);
    int m  = a * GG + sI;

    const float4* dr = reinterpret_cast<const float4*>(&g_det[((size_t)b * NBOX + m) * 8]);
    float4 d0 = dr[0], d1 = dr[1];
    float cls = d1.z;
    float off = __fmul_rn(cls, 10000.0f);
    float sx1 = __fadd_rn(d0.x, off);
    float sy1 = __fadd_rn(d0.y, off);
    float sx2 = __fadd_rn(d0.z, off);
    float sy2 = __fadd_rn(d0.w, off);
    float area = __fmul_rn(__fsub_rn(sx2, sx1), __fsub_rn(sy2, sy1));

    float4* cr = reinterpret_cast<float4*>(&g_cand[((size_t)b * TOPK + tid) * 8]);
    cr[0] = make_float4(sx1, sy1, sx2, sy2);
    cr[1] = make_float4(area, cls, valid ? 1.0f : 0.0f, 0.0f);
    g_topidx[b * TOPK + tid] = m;

    unsigned vb2 = __ballot_sync(0xffffffffu, valid);
    if (lane == 0) g_validbits[b * 32 + warp] = vb2;
}

// -------------------- K3: pairwise suppression bitmask ----------------------
// grid (32 row-tiles, 32 images), 1024 threads = 32 warps.
// Warp r handles row i = rt*32+r; lane owns column j = w*32+lane each step:
// consecutive-j shared loads (conflict-free) + __ballot_sync builds the word.
__global__ void k_mask()
{
    int rt  = blockIdx.x;
    int b   = blockIdx.y;
    int tid = threadIdx.x;
    int warp = tid >> 5;
    int lane = tid & 31;

    __shared__ float sx1[TOPK], sy1[TOPK], sx2[TOPK], sy2[TOPK], sar[TOPK], scl[TOPK];
    __shared__ unsigned s_any[32];

    for (int e = tid; e < TOPK; e += 1024) {
        const float4* cr = reinterpret_cast<const float4*>(&g_cand[((size_t)b * TOPK + e) * 8]);
        float4 c0 = cr[0], c1 = cr[1];
        sx1[e] = c0.x; sy1[e] = c0.y; sx2[e] = c0.z;
        sy2[e] = c0.w; sar[e] = c1.x; scl[e] = c1.y;
    }
    __syncthreads();

    int i = rt * 32 + warp;
    float ax1 = sx1[i], ay1 = sy1[i], ax2 = sx2[i], ay2 = sy2[i];
    float aa = sar[i], ac = scl[i];

    unsigned myword = 0;
    #pragma unroll 4
    for (int w = 0; w < 32; w++) {
        int j = (w << 5) + lane;
        bool sup = false;
        if (j > i && scl[j] == ac) {   // class offset 10000 => cross-class IoU can never pass
            float lx = fmaxf(ax1, sx1[j]);
            float ly = fmaxf(ay1, sy1[j]);
            float rx = fminf(ax2, sx2[j]);
            float ry = fminf(ay2, sy2[j]);
            float ww = fmaxf(__fsub_rn(rx, lx), 0.0f);
            float hh = fmaxf(__fsub_rn(ry, ly), 0.0f);
            float inter = __fmul_rn(ww, hh);
            float denom = __fadd_rn(__fsub_rn(__fadd_rn(aa, sar[j]), inter), 1e-9f);
            float iou   = __fdiv_rn(inter, denom);
            sup = iou > 0.4f;
        }
        unsigned word = __ballot_sync(0xffffffffu, sup);
        if (w == lane) myword = word;
    }
    g_mask[(((size_t)b * TOPK) + i) * 32 + lane] = myword;

    unsigned nzb = __ballot_sync(0xffffffffu, myword != 0u);
    if (lane == 0) s_any[warp] = nzb;
    __syncthreads();
    if (warp == 0) {
        unsigned bits = __ballot_sync(0xffffffffu, s_any[lane] != 0u);
        if (lane == 0) g_rownz[b * 32 + rt] = bits;
    }
}

// -------------------- K4: resolve + emit (fused, 1 block/image) -------------
__global__ void k_final(float* __restrict__ out, int out_size)
{
    int b   = blockIdx.x;
    int tid = threadIdx.x;   // 1024 threads

    __shared__ unsigned       s_rem[32];
    __shared__ unsigned short s_rows[TOPK];
    __shared__ int            s_R;
    __shared__ unsigned       s_masks[256][32];

    // ordered list of nonzero-mask rows (warp 0)
    if (tid < 32) {
        unsigned nz = g_rownz[b * 32 + tid];
        int cnt = __popc(nz);
        int inc = cnt;
        #pragma unroll
        for (int off = 1; off < 32; off <<= 1) {
            int v = __shfl_up_sync(0xffffffffu, inc, off);
            if (tid >= off) inc += v;
        }
        int o = inc - cnt;
        unsigned t = nz;
        while (t) { int r = __ffs(t) - 1; t &= t - 1; s_rows[o++] = (unsigned short)(tid * 32 + r); }
        if (tid == 31) s_R = inc;
    }
    __syncthreads();
    int R  = s_R;
    int RL = R < 256 ? R : 256;

    // parallel preload of the (few) needed mask rows
    for (int t = tid; t < RL * 32; t += 1024)
        s_masks[t >> 5][t & 31] = g_mask[((size_t)b * TOPK + s_rows[t >> 5]) * 32 + (t & 31)];
    __syncthreads();

    // serial resolve (1 warp, register-resident state)
    if (tid < 32) {
        int lane = tid;
        unsigned rem = 0;
        unsigned validw = g_validbits[b * 32 + lane];
        for (int k2 = 0; k2 < R; k2++) {
            int i = s_rows[k2];
            unsigned w  = __shfl_sync(0xffffffffu, rem,    i >> 5);
            unsigned vw = __shfl_sync(0xffffffffu, validw, i >> 5);
            bool act = !((w >> (i & 31)) & 1u) && ((vw >> (i & 31)) & 1u);
            if (act)
                rem |= (k2 < 256) ? s_masks[k2][lane]
                                  : g_mask[((size_t)b * TOPK + i) * 32 + lane];
        }
        s_rem[lane] = rem;
    }
    __syncthreads();

    // emit
    int j = tid;
    bool keep = ((g_validbits[b * 32 + (j >> 5)] >> (j & 31)) & 1u)
             && !((s_rem[j >> 5] >> (j & 31)) & 1u);

    int m = g_topidx[b * TOPK + j];
    const float4* dr = reinterpret_cast<const float4*>(&g_det[((size_t)b * NBOX + m) * 8]);
    float4 d0 = dr[0], d1 = dr[1];
    float o7[7] = {d0.x, d0.y, d0.z, d0.w, d1.x, d1.y, d1.z};

    size_t basep = ((size_t)b * TOPK + j) * 7;
    #pragma unroll
    for (int k = 0; k < 7; k++)
        out[basep + k] = keep ? __fmul_rn(8.0f, o7[k]) : 0.0f;

    if (out_size >= BATCH * TOPK * 7 + BATCH * TOPK)
        out[(size_t)BATCH * TOPK * 7 + (size_t)b * TOPK + j] = keep ? 1.0f : 0.0f;
}

// -------------------- launch -----------------------------------------------
extern "C" void kernel_launch(void* const* d_in, const int* in_sizes, int n_in,
                              void* d_out, int out_size)
{
    const float* in = (const float*)d_in[0];
    float* out = (float*)d_out;

    k_decode<<<dim3(8, 3, BATCH), 128>>>(in);
    k_select<<<BATCH, 1024>>>();
    k_mask<<<dim3(32, BATCH), 1024>>>();
    k_final<<<BATCH, 1024>>>(out, out_size);
}